// round 1
// baseline (speedup 1.0000x reference)
#include <cuda_runtime.h>

#define TILE 32
#define LDI 37   // row stride for 36-wide I/p tiles (odd -> conflict-free)
#define LDA 35   // row stride for 34-wide a/b tiles

__global__ __launch_bounds__(1024, 2)
void guided_filter_kernel(const float* __restrict__ I,
                          const float* __restrict__ P,
                          float* __restrict__ O,
                          int H, int W) {
    __shared__ float sI[36 * LDI];
    __shared__ float sP[36 * LDI];
    __shared__ float sA[34 * LDA];
    __shared__ float sB[34 * LDA];

    const int bx = blockIdx.x * TILE;
    const int by = blockIdx.y * TILE;
    const long long base = (long long)blockIdx.z * H * W;
    const int tid = threadIdx.y * 32 + threadIdx.x;

    // ---- Stage 1: load (TILE+4)x(TILE+4) halo of I and p (zero OOB) ----
    #pragma unroll
    for (int i = tid; i < 36 * 36; i += 1024) {
        const int ly = i / 36;
        const int lx = i - ly * 36;
        const int gx = bx + lx - 2;
        const int gy = by + ly - 2;
        float vi = 0.0f, vp = 0.0f;
        if (gx >= 0 && gx < W && gy >= 0 && gy < H) {
            const long long idx = base + (long long)gy * W + gx;
            vi = I[idx];
            vp = P[idx];
        }
        sI[ly * LDI + lx] = vi;
        sP[ly * LDI + lx] = vp;
    }
    __syncthreads();

    // ---- Stage 2: compute a,b on (TILE+2)x(TILE+2) inner region ----
    #pragma unroll
    for (int i = tid; i < 34 * 34; i += 1024) {
        const int ly = i / 34;
        const int lx = i - ly * 34;
        const int gx = bx + lx - 1;
        const int gy = by + ly - 1;
        float a = 0.0f, b = 0.0f;
        if (gx >= 0 && gx < W && gy >= 0 && gy < H) {
            float sumI = 0.f, sumP = 0.f, sumII = 0.f, sumIP = 0.f;
            #pragma unroll
            for (int dy = 0; dy < 3; dy++) {
                #pragma unroll
                for (int dx = 0; dx < 3; dx++) {
                    const float vi = sI[(ly + dy) * LDI + (lx + dx)];
                    const float vp = sP[(ly + dy) * LDI + (lx + dx)];
                    sumI  += vi;
                    sumP  += vp;
                    sumII += vi * vi;
                    sumIP += vi * vp;
                }
            }
            // count_include_pad=False window counts
            const int cx = min(gx + 1, W - 1) - max(gx - 1, 0) + 1;
            const int cy = min(gy + 1, H - 1) - max(gy - 1, 0) + 1;
            const float inv = 1.0f / (float)(cx * cy);
            const float mI = sumI * inv;
            const float mP = sumP * inv;
            const float varI  = sumII * inv - mI * mI;
            const float covIP = sumIP * inv - mI * mP;
            a = covIP / (varI + 0.01f);
            b = mP - a * mI;
        }
        sA[ly * LDA + lx] = a;
        sB[ly * LDA + lx] = b;
    }
    __syncthreads();

    // ---- Stage 3: blur a,b over 3x3, combine with I ----
    const int lx = threadIdx.x;
    const int ly = threadIdx.y;
    const int gx = bx + lx;
    const int gy = by + ly;
    if (gx < W && gy < H) {
        float sa = 0.f, sb = 0.f;
        #pragma unroll
        for (int dy = 0; dy < 3; dy++) {
            #pragma unroll
            for (int dx = 0; dx < 3; dx++) {
                sa += sA[(ly + dy) * LDA + (lx + dx)];
                sb += sB[(ly + dy) * LDA + (lx + dx)];
            }
        }
        const int cx = min(gx + 1, W - 1) - max(gx - 1, 0) + 1;
        const int cy = min(gy + 1, H - 1) - max(gy - 1, 0) + 1;
        const float inv = 1.0f / (float)(cx * cy);
        const float vi = sI[(ly + 2) * LDI + (lx + 2)];
        O[base + (long long)gy * W + gx] = (sa * inv) * vi + (sb * inv);
    }
}

extern "C" void kernel_launch(void* const* d_in, const int* in_sizes, int n_in,
                              void* d_out, int out_size) {
    const float* I = (const float*)d_in[0];   // input
    const float* P = (const float*)d_in[1];   // guide
    float* O = (float*)d_out;

    const int H = 512, W = 512;
    const int Z = in_sizes[0] / (H * W);      // B*C = 128

    dim3 block(32, 32, 1);
    dim3 grid(W / TILE, H / TILE, Z);
    guided_filter_kernel<<<grid, block>>>(I, P, O, H, W);
}

// round 2
// speedup vs baseline: 2.5759x; 2.5759x over previous
#include <cuda_runtime.h>

#define Wd 512
#define Hd 512
#define NT 128          // threads per CTA; each owns 4 contiguous x (float4)
#define RSTRIP 68       // output rows per CTA strip
#define NITER 72        // RSTRIP + 4 (2 halo rows top, 2 pipeline+halo bottom)
#define THIRD 0.33333333333333333f

__device__ __forceinline__ float4 hsum3(float l, float4 v, float r) {
    // 3-tap horizontal sums for the 4 lanes, sharing partial sums
    float t1 = v.x + v.y;
    float t2 = v.y + v.z;
    float t3 = v.z + v.w;
    return make_float4(l + t1, t1 + v.z, t2 + v.w, t3 + r);
}
__device__ __forceinline__ float4 f4add(float4 a, float4 b) {
    return make_float4(a.x + b.x, a.y + b.y, a.z + b.z, a.w + b.w);
}

__global__ __launch_bounds__(NT, 4)
void gf_kernel(const float* __restrict__ gI, const float* __restrict__ gP,
               float* __restrict__ gO)
{
    __shared__ float sI[Wd], sP[Wd], sA[Wd], sB[Wd];

    const int t  = threadIdx.x;
    const int x0 = t * 4;
    const int y0 = blockIdx.x * RSTRIP;
    const size_t base = (size_t)blockIdx.y * (size_t)(Wd * Hd);
    const float4* GI = (const float4*)(gI + base);
    const float4* GP = (const float4*)(gP + base);
    float4*       GO = (float4*)(gO + base);

    // per-lane 1/cx (count_include_pad=False horizontal counts)
    float4 invcx = make_float4(THIRD, THIRD, THIRD, THIRD);
    if (t == 0)      invcx.x = 0.5f;
    if (t == NT - 1) invcx.w = 0.5f;

    const float4 z4 = make_float4(0.f, 0.f, 0.f, 0.f);

    // Vertical sliding state per quantity: pair-sum of the two previous
    // h-rows + the previous h-row itself. 3-row sum = ps + h_new.
    float4 psI = z4, lI = z4;
    float4 psP = z4, lP = z4;
    float4 psII = z4, lII = z4;
    float4 psIP = z4, lIP = z4;
    float4 psA = z4, lA = z4;
    float4 psB = z4, lB = z4;
    float4 rI[3] = {z4, z4, z4};   // raw I rows, need the one from 2 iters back

    for (int ib = 0; ib < NITER; ib += 3) {
        #pragma unroll
        for (int c = 0; c < 3; ++c) {
            const int i = ib + c;

            // ---------- stage 1: load input row, horizontal sums ----------
            const int yin = y0 - 2 + i;
            float4 vi = z4, vp = z4;
            if (yin >= 0 && yin < Hd) {
                vi = GI[(size_t)yin * (Wd / 4) + t];
                vp = GP[(size_t)yin * (Wd / 4) + t];
            }
            rI[c] = vi;
            ((float4*)sI)[t] = vi;
            ((float4*)sP)[t] = vp;
            __syncthreads();
            const float iL = (t > 0)      ? sI[x0 - 1] : 0.f;
            const float iR = (t < NT - 1) ? sI[x0 + 4] : 0.f;
            const float pL = (t > 0)      ? sP[x0 - 1] : 0.f;
            const float pR = (t < NT - 1) ? sP[x0 + 4] : 0.f;

            float4 hI = hsum3(iL, vi, iR);
            float4 hP = hsum3(pL, vp, pR);
            float4 hII, hIP;
            {
                float q0 = iL * iL, q1 = vi.x * vi.x, q2 = vi.y * vi.y;
                float q3 = vi.z * vi.z, q4 = vi.w * vi.w, q5 = iR * iR;
                hII = make_float4(q0 + q1 + q2, q1 + q2 + q3, q2 + q3 + q4, q3 + q4 + q5);
                float r0 = iL * pL, r1 = vi.x * vp.x, r2 = vi.y * vp.y;
                float r3 = vi.z * vp.z, r4 = vi.w * vp.w, r5 = iR * pR;
                hIP = make_float4(r0 + r1 + r2, r1 + r2 + r3, r2 + r3 + r4, r3 + r4 + r5);
            }

            // vertical 3-row sums via pair-sum sliding window
            float4 SI  = f4add(psI,  hI);
            float4 SP  = f4add(psP,  hP);
            float4 SII = f4add(psII, hII);
            float4 SIP = f4add(psIP, hIP);
            psI  = f4add(lI,  hI);   lI  = hI;
            psP  = f4add(lP,  hP);   lP  = hP;
            psII = f4add(lII, hII);  lII = hII;
            psIP = f4add(lIP, hIP);  lIP = hIP;

            // ---------- stage 2: a,b for row ra ----------
            const int ra = y0 + i - 3;
            float4 av = z4, bv = z4;
            if (ra >= 0 && ra < Hd) {
                const float invcy = (ra == 0 || ra == Hd - 1) ? 0.5f : THIRD;
                #define LANE(L) { \
                    float inv = invcx.L * invcy; \
                    float mI = SI.L * inv, mP = SP.L * inv; \
                    float var = fmaf(SII.L, inv, -mI * mI); \
                    float cov = fmaf(SIP.L, inv, -mI * mP); \
                    float a = __fdividef(cov, var + 0.01f); \
                    av.L = a; bv.L = fmaf(-a, mI, mP); }
                LANE(x) LANE(y) LANE(z) LANE(w)
                #undef LANE
            }
            ((float4*)sA)[t] = av;
            ((float4*)sB)[t] = bv;
            __syncthreads();
            const float aL = (t > 0)      ? sA[x0 - 1] : 0.f;
            const float aR = (t < NT - 1) ? sA[x0 + 4] : 0.f;
            const float bL = (t > 0)      ? sB[x0 - 1] : 0.f;
            const float bR = (t < NT - 1) ? sB[x0 + 4] : 0.f;

            float4 hA = hsum3(aL, av, aR);
            float4 hB = hsum3(bL, bv, bR);
            float4 SA = f4add(psA, hA);
            float4 SB = f4add(psB, hB);
            psA = f4add(lA, hA);  lA = hA;
            psB = f4add(lB, hB);  lB = hB;

            // ---------- stage 3: output row ro ----------
            const int ro = y0 + i - 4;
            if (i >= 4 && ro < Hd) {
                const float invcy = (ro == 0 || ro == Hd - 1) ? 0.5f : THIRD;
                const float4 vO = rI[(c + 1) % 3];  // I row loaded 2 iters ago
                float4 o;
                o.x = fmaf(SA.x, vO.x, SB.x) * (invcx.x * invcy);
                o.y = fmaf(SA.y, vO.y, SB.y) * (invcx.y * invcy);
                o.z = fmaf(SA.z, vO.z, SB.z) * (invcx.z * invcy);
                o.w = fmaf(SA.w, vO.w, SB.w) * (invcx.w * invcy);
                GO[(size_t)ro * (Wd / 4) + t] = o;
            }
        }
    }
}

extern "C" void kernel_launch(void* const* d_in, const int* in_sizes, int n_in,
                              void* d_out, int out_size) {
    const float* I = (const float*)d_in[0];   // input
    const float* P = (const float*)d_in[1];   // guide
    float* O = (float*)d_out;

    const int Z = in_sizes[0] / (Wd * Hd);    // B*C = 128
    const int strips = (Hd + RSTRIP - 1) / RSTRIP;  // 8

    dim3 block(NT, 1, 1);
    dim3 grid(strips, Z, 1);
    gf_kernel<<<grid, block>>>(I, P, O);
}

// round 3
// speedup vs baseline: 2.9220x; 1.1344x over previous
#include <cuda_runtime.h>

#define Wd 512
#define Hd 512
#define NT 256                 // threads per CTA; each owns 2 contiguous x (float2)
#define RSTRIP 64              // output rows per CTA
#define NITER (RSTRIP + 5)     // pipeline depth 5: 2 top halo + 3 stage latency
#define THIRD 0.3333333333333333f

__global__ __launch_bounds__(NT, 4)
void gf_kernel(const float* __restrict__ gI, const float* __restrict__ gP,
               float* __restrict__ gO)
{
    // double-buffered exchange rows (one __syncthreads per iteration)
    __shared__ float sI[2][Wd], sP[2][Wd], sA[2][Wd], sB[2][Wd];

    const int t  = threadIdx.x;
    const int x0 = 2 * t;
    const int y0 = blockIdx.x * RSTRIP;
    const size_t base = (size_t)blockIdx.y * (size_t)(Wd * Hd);
    const float2* __restrict__ GI = (const float2*)(gI + base);
    const float2* __restrict__ GP = (const float2*)(gP + base);
    float2* __restrict__ GO = (float2*)(gO + base);

    // count_include_pad=False horizontal reciprocal counts for this thread's 2 cols
    const float icx0 = (t == 0)      ? 0.5f : THIRD;
    const float icx1 = (t == NT - 1) ? 0.5f : THIRD;

    // vertical sliding state: pair-sum (ps) of previous two h-rows + last h-row (l)
    float psIx=0,psIy=0,lIx=0,lIy=0;
    float psPx=0,psPy=0,lPx=0,lPy=0;
    float psIIx=0,psIIy=0,lIIx=0,lIIy=0;
    float psIPx=0,psIPy=0,lIPx=0,lIPy=0;
    float psAx=0,psAy=0,lAx=0,lAy=0;
    float psBx=0,psBy=0,lBx=0,lBy=0;
    float avPx=0,avPy=0,bvPx=0,bvPy=0;   // a/b row computed last iter (awaiting exchange)

    // prologue: rows y0-2 (current) and y0-1 (next)
    float2 viC={0.f,0.f}, vpC={0.f,0.f}, viN={0.f,0.f}, vpN={0.f,0.f};
    if (y0 - 2 >= 0) { viC = GI[(y0-2)*(Wd/2)+t]; vpC = GP[(y0-2)*(Wd/2)+t]; }
    if (y0 - 1 >= 0) { viN = GI[(y0-1)*(Wd/2)+t]; vpN = GP[(y0-1)*(Wd/2)+t]; }

    ((float2*)sI[0])[t] = viC;
    ((float2*)sP[0])[t] = vpC;
    ((float2*)sA[0])[t] = make_float2(0.f, 0.f);
    ((float2*)sB[0])[t] = make_float2(0.f, 0.f);
    __syncthreads();

    int p = 0;
    for (int i = 0; i < NITER; ++i) {
        const int q = p ^ 1;

        // ---- neighbor reads from buffer p ----
        const float iL = (t > 0)      ? sI[p][x0-1] : 0.f;
        const float iR = (t < NT - 1) ? sI[p][x0+2] : 0.f;
        const float pL = (t > 0)      ? sP[p][x0-1] : 0.f;
        const float pR = (t < NT - 1) ? sP[p][x0+2] : 0.f;
        const float aL = (t > 0)      ? sA[p][x0-1] : 0.f;
        const float aR = (t < NT - 1) ? sA[p][x0+2] : 0.f;
        const float bL = (t > 0)      ? sB[p][x0-1] : 0.f;
        const float bR = (t < NT - 1) ? sB[p][x0+2] : 0.f;

        // ---- prefetch input row y0+i (consumed at iter i+2) ----
        float2 vi2 = {0.f,0.f}, vp2 = {0.f,0.f};
        const int rn = y0 + i;
        if (rn < Hd) { vi2 = GI[rn*(Wd/2)+t]; vp2 = GP[rn*(Wd/2)+t]; }

        // ---- horizontal 3-sums for input row y0-2+i ----
        const float mi  = viC.x + viC.y;
        const float hIx = iL + mi,  hIy = mi + iR;
        const float mp  = vpC.x + vpC.y;
        const float hPx = pL + mp,  hPy = mp + pR;
        const float mii = viC.x*viC.x + viC.y*viC.y;
        const float hIIx = fmaf(iL, iL, mii), hIIy = fmaf(iR, iR, mii);
        const float mip = viC.x*vpC.x + viC.y*vpC.y;
        const float hIPx = fmaf(iL, pL, mip), hIPy = fmaf(iR, pR, mip);

        // ---- vertical 3-row sums via pair-sum slide ----
        const float SIx  = psIx  + hIx,  SIy  = psIy  + hIy;
        const float SPx  = psPx  + hPx,  SPy  = psPy  + hPy;
        const float SIIx = psIIx + hIIx, SIIy = psIIy + hIIy;
        const float SIPx = psIPx + hIPx, SIPy = psIPy + hIPy;
        psIx  = lIx  + hIx;  lIx  = hIx;  psIy  = lIy  + hIy;  lIy  = hIy;
        psPx  = lPx  + hPx;  lPx  = hPx;  psPy  = lPy  + hPy;  lPy  = hPy;
        psIIx = lIIx + hIIx; lIIx = hIIx; psIIy = lIIy + hIIy; lIIy = hIIy;
        psIPx = lIPx + hIPx; lIPx = hIPx; psIPy = lIPy + hIPy; lIPy = hIPy;

        // ---- a,b for row ra = y0+i-3 ----
        float avx = 0.f, avy = 0.f, bvx = 0.f, bvy = 0.f;
        const int ra = y0 + i - 3;
        if ((unsigned)ra < (unsigned)Hd) {
            const float invcy = (ra == 0 || ra == Hd - 1) ? 0.5f : THIRD;
            {
                const float inv = icx0 * invcy;
                const float mI = SIx * inv, mP = SPx * inv;
                const float var = fmaf(SIIx, inv, -mI * mI);
                const float cov = fmaf(SIPx, inv, -mI * mP);
                const float a = __fdividef(cov, var + 0.01f);
                avx = a; bvx = fmaf(-a, mI, mP);
            }
            {
                const float inv = icx1 * invcy;
                const float mI = SIy * inv, mP = SPy * inv;
                const float var = fmaf(SIIy, inv, -mI * mI);
                const float cov = fmaf(SIPy, inv, -mI * mP);
                const float a = __fdividef(cov, var + 0.01f);
                avy = a; bvy = fmaf(-a, mI, mP);
            }
        }

        // ---- exchange + vertical slide for a/b row y0+i-4 (regs + smem neighbors) ----
        const float ma  = avPx + avPy;
        const float hAx = aL + ma, hAy = ma + aR;
        const float mb  = bvPx + bvPy;
        const float hBx = bL + mb, hBy = mb + bR;
        const float SAx = psAx + hAx, SAy = psAy + hAy;
        const float SBx = psBx + hBx, SBy = psBy + hBy;
        psAx = lAx + hAx; lAx = hAx; psAy = lAy + hAy; lAy = hAy;
        psBx = lBx + hBx; lBx = hBx; psBy = lBy + hBy; lBy = hBy;

        // ---- output row ro = y0+i-5 ----
        if (i >= 5) {
            const int ro = y0 + i - 5;
            const float invcy = (ro == 0 || ro == Hd - 1) ? 0.5f : THIRD;
            const float2 vO = __ldg(&GI[ro*(Wd/2)+t]);   // L1 hit (loaded 3 iters ago)
            float2 o;
            o.x = fmaf(SAx, vO.x, SBx) * (icx0 * invcy);
            o.y = fmaf(SAy, vO.y, SBy) * (icx1 * invcy);
            GO[ro*(Wd/2)+t] = o;
        }

        // ---- stage writes for next iteration ----
        ((float2*)sI[q])[t] = viN;
        ((float2*)sP[q])[t] = vpN;
        ((float2*)sA[q])[t] = make_float2(avx, avy);
        ((float2*)sB[q])[t] = make_float2(bvx, bvy);

        avPx = avx; avPy = avy; bvPx = bvx; bvPy = bvy;
        viC = viN; vpC = vpN; viN = vi2; vpN = vp2;

        __syncthreads();
        p = q;
    }
}

extern "C" void kernel_launch(void* const* d_in, const int* in_sizes, int n_in,
                              void* d_out, int out_size) {
    const float* I = (const float*)d_in[0];   // input
    const float* P = (const float*)d_in[1];   // guide
    float* O = (float*)d_out;

    const int Z = in_sizes[0] / (Wd * Hd);    // B*C = 128
    const int strips = Hd / RSTRIP;           // 8

    dim3 block(NT, 1, 1);
    dim3 grid(strips, Z, 1);
    gf_kernel<<<grid, block>>>(I, P, O);
}

// round 7
// speedup vs baseline: 3.4894x; 1.1942x over previous
#include <cuda_runtime.h>

#define Wd 512
#define Hd 512
#define W2 (Wd / 2)
#define NT 256
#define RSTRIP 64
#define LDW 520            // padded row: [0,1] left guard, data [2..513], [514..] right guard
#define THIRD 0.3333333333333333f
#define EPS 0.01f

typedef unsigned long long ull;

static __device__ __forceinline__ ull U(float2 v) { ull r; memcpy(&r, &v, 8); return r; }
static __device__ __forceinline__ float2 F(ull u) { float2 v; memcpy(&v, &u, 8); return v; }

static __device__ __forceinline__ float2 f2add(float2 a, float2 b) {
    ull r; asm("add.rn.f32x2 %0,%1,%2;" : "=l"(r) : "l"(U(a)), "l"(U(b))); return F(r);
}
static __device__ __forceinline__ float2 f2mul(float2 a, float2 b) {
    ull r; asm("mul.rn.f32x2 %0,%1,%2;" : "=l"(r) : "l"(U(a)), "l"(U(b))); return F(r);
}
static __device__ __forceinline__ float2 f2fma(float2 a, float2 b, float2 c) {
    ull r; asm("fma.rn.f32x2 %0,%1,%2,%3;" : "=l"(r) : "l"(U(a)), "l"(U(b)), "l"(U(c))); return F(r);
}
static __device__ __forceinline__ float2 mk2(float a, float b) { float2 v; v.x = a; v.y = b; return v; }

__global__ __launch_bounds__(NT, 4)
void gf_kernel(const float* __restrict__ gI, const float* __restrict__ gP,
               float* __restrict__ gO)
{
    __shared__ __align__(16) float smI[2][LDW], smP[2][LDW], smA[2][LDW], smB[2][LDW];

    const int t  = threadIdx.x;
    const int x0 = 2 * t;                 // padded data index of own pair = x0+2
    const int y0 = blockIdx.x * RSTRIP;
    const size_t base = (size_t)blockIdx.y * (size_t)(Wd * Hd);
    const float2* __restrict__ GI = (const float2*)(gI + base);
    const float2* __restrict__ GP = (const float2*)(gP + base);
    float2* __restrict__ GO = (float2*)(gO + base);

    const float icx0 = (t == 0)      ? 0.5f : THIRD;   // count_include_pad=False col counts
    const float icx1 = (t == NT - 1) ? 0.5f : THIRD;

    // permanent zero guards (stores each iter touch only [2..513])
    if (t < 2) {
        const int g = (t == 0) ? 1 : 514;
        #pragma unroll
        for (int b = 0; b < 2; ++b) {
            smI[b][g] = 0.f; smP[b][g] = 0.f; smA[b][g] = 0.f; smB[b][g] = 0.f;
        }
    }

    const float2 z2 = mk2(0.f, 0.f);

    // vertical sliding state (pair-sum ps + last h-row l), all packed float2
    float2 psI = z2, lI = z2, psP = z2, lP = z2;
    float2 psII = z2, lII = z2, psIP = z2, lIP = z2;
    float2 psA = z2, lA = z2, psB = z2, lB = z2;
    float2 avP = z2, bvP = z2;

    // prologue rows y0-2 (cur) and y0-1 (next)
    float2 viC = z2, vpC = z2, viN = z2, vpN = z2;
    if (y0 >= 2) {
        viC = GI[(y0 - 2) * W2 + t]; vpC = GP[(y0 - 2) * W2 + t];
        viN = GI[(y0 - 1) * W2 + t]; vpN = GP[(y0 - 1) * W2 + t];
    }
    ((float2*)&smI[0][2])[t] = viC;
    ((float2*)&smP[0][2])[t] = vpC;
    ((float2*)&smA[0][2])[t] = z2;
    ((float2*)&smB[0][2])[t] = z2;
    __syncthreads();

    int rn   = y0;            // row prefetched this body
    int ra   = y0 - 3;        // a/b row produced this body
    int ro   = y0 - 5;        // output row produced this body
    int oidx = y0 * W2 + t;   // output / output-I index (advances in main bodies)

#define BODY(P, DO_OUT)                                                          \
    {                                                                            \
        /* neighbor pair reads (aligned LDS.64, guards make edges zero) */       \
        const float2 vLI = *(const float2*)&smI[P][x0];                          \
        const float2 vRI = *(const float2*)&smI[P][x0 + 4];                      \
        const float2 vLP = *(const float2*)&smP[P][x0];                          \
        const float2 vRP = *(const float2*)&smP[P][x0 + 4];                      \
        const float2 vLA = *(const float2*)&smA[P][x0];                          \
        const float2 vRA = *(const float2*)&smA[P][x0 + 4];                      \
        const float2 vLB = *(const float2*)&smB[P][x0];                          \
        const float2 vRB = *(const float2*)&smB[P][x0 + 4];                      \
        /* prefetch input row rn (consumed 2 bodies later) */                    \
        float2 viF = z2, vpF = z2;                                               \
        if (rn < Hd) { viF = GI[rn * W2 + t]; vpF = GP[rn * W2 + t]; }           \
        rn++;                                                                    \
        /* shifted pairs for row viC/vpC */                                      \
        const float2 sLI = mk2(vLI.y, viC.x), sRI = mk2(viC.y, vRI.x);           \
        const float2 sLP = mk2(vLP.y, vpC.x), sRP = mk2(vpC.y, vRP.x);           \
        /* horizontal 3-sums (packed) */                                         \
        const float2 hI  = f2add(f2add(sLI, viC), sRI);                          \
        const float2 hP  = f2add(f2add(sLP, vpC), sRP);                          \
        const float2 hII = f2fma(sLI, sLI, f2fma(viC, viC, f2mul(sRI, sRI)));    \
        const float2 hIP = f2fma(sLI, sLP, f2fma(viC, vpC, f2mul(sRI, sRP)));    \
        /* vertical 3-row slide (packed) */                                      \
        const float2 SI  = f2add(psI,  hI);  psI  = f2add(lI,  hI);  lI  = hI;   \
        const float2 SP  = f2add(psP,  hP);  psP  = f2add(lP,  hP);  lP  = hP;   \
        const float2 SII = f2add(psII, hII); psII = f2add(lII, hII); lII = hII;  \
        const float2 SIP = f2add(psIP, hIP); psIP = f2add(lIP, hIP); lIP = hIP;  \
        /* a,b for row ra; rows outside [0,Hd) MUST be zero (ra=Hd sums rows    \
           Hd-1..Hd+1 which are NOT all zero) */                                 \
        const float invcyA = (ra == 0 || ra == Hd - 1) ? 0.5f : THIRD;           \
        const bool raOK = ((unsigned)ra < (unsigned)Hd);                         \
        ra++;                                                                    \
        float2 av = z2, bv = z2;                                                 \
        if (raOK) {                                                              \
            {                                                                    \
                const float inv = icx0 * invcyA;                                 \
                const float mI = SI.x * inv, mP = SP.x * inv;                    \
                const float var = fmaf(SII.x, inv, -mI * mI);                    \
                const float cov = fmaf(SIP.x, inv, -mI * mP);                    \
                const float a = __fdividef(cov, var + EPS);                      \
                av.x = a; bv.x = fmaf(-a, mI, mP);                               \
            }                                                                    \
            {                                                                    \
                const float inv = icx1 * invcyA;                                 \
                const float mI = SI.y * inv, mP = SP.y * inv;                    \
                const float var = fmaf(SII.y, inv, -mI * mI);                    \
                const float cov = fmaf(SIP.y, inv, -mI * mP);                    \
                const float a = __fdividef(cov, var + EPS);                      \
                av.y = a; bv.y = fmaf(-a, mI, mP);                               \
            }                                                                    \
        }                                                                        \
        /* a/b h-sums for row staged last body (avP) + vertical slide */         \
        const float2 sLA = mk2(vLA.y, avP.x), sRA = mk2(avP.y, vRA.x);           \
        const float2 sLB = mk2(vLB.y, bvP.x), sRB = mk2(bvP.y, vRB.x);           \
        const float2 hA = f2add(f2add(sLA, avP), sRA);                           \
        const float2 hB = f2add(f2add(sLB, bvP), sRB);                           \
        const float2 SA = f2add(psA, hA); psA = f2add(lA, hA); lA = hA;          \
        const float2 SB = f2add(psB, hB); psB = f2add(lB, hB); lB = hB;          \
        /* output row ro */                                                      \
        if (DO_OUT) {                                                            \
            const float invcyO = (ro == 0 || ro == Hd - 1) ? 0.5f : THIRD;       \
            const float2 vO = __ldg(&GI[oidx]);                                  \
            const float2 sc = mk2(icx0 * invcyO, icx1 * invcyO);                 \
            GO[oidx] = f2mul(f2fma(SA, vO, SB), sc);                             \
            oidx += W2;                                                          \
        }                                                                        \
        ro++;                                                                    \
        /* stage next buffer */                                                  \
        ((float2*)&smI[P ^ 1][2])[t] = viN;                                      \
        ((float2*)&smP[P ^ 1][2])[t] = vpN;                                      \
        ((float2*)&smA[P ^ 1][2])[t] = av;                                       \
        ((float2*)&smB[P ^ 1][2])[t] = bv;                                       \
        avP = av; bvP = bv;                                                      \
        viC = viN; vpC = vpN; viN = viF; vpN = vpF;                              \
        __syncthreads();                                                         \
    }

    // prologue: i = 0..4 (no outputs), parities 0,1,0,1,0
    BODY(0, false) BODY(1, false) BODY(0, false) BODY(1, false) BODY(0, false)

    // main: i = 5..68 (64 outputs), parities 1,0 repeated
    for (int k = 0; k < 32; ++k) {
        BODY(1, true)
        BODY(0, true)
    }
#undef BODY
}

extern "C" void kernel_launch(void* const* d_in, const int* in_sizes, int n_in,
                              void* d_out, int out_size) {
    const float* I = (const float*)d_in[0];   // input
    const float* P = (const float*)d_in[1];   // guide
    float* O = (float*)d_out;

    const int Z = in_sizes[0] / (Wd * Hd);    // B*C = 128
    dim3 block(NT, 1, 1);
    dim3 grid(Hd / RSTRIP, Z, 1);             // 8 x 128
    gf_kernel<<<grid, block>>>(I, P, O);
}